// round 16
// baseline (speedup 1.0000x reference)
#include <cuda_runtime.h>
#include <cuda_fp16.h>
#include <cstdint>

#define TOK 4096
#define HID 1024
#define KVW 256
#define SEQ 2048

// fp32 scratch
__device__ float g_t1[TOK * HID];
__device__ float g_o [TOK * HID];
// fp16 scratch
__device__ __half g_hh [TOK * HID];
__device__ __half g_wqh[HID * HID];
__device__ __half g_wkh[KVW * HID];
__device__ __half g_wvh[KVW * HID];
__device__ __half g_woh[HID * HID];
__device__ __half g_w1h[HID * HID];
__device__ __half g_w2h[HID * HID];
__device__ __half g_qh [TOK * HID];
__device__ __half g_kh [TOK * KVW];
__device__ __half g_vh [TOK * KVW];
__device__ __half g_xh [TOK * HID];
__device__ __half g_oh [TOK * HID];
__device__ __half g_f1h[TOK * HID];

__device__ __forceinline__ unsigned su32(const void* p) {
    return (unsigned)__cvta_generic_to_shared(p);
}
__device__ __forceinline__ void cp16(unsigned s, const void* g) {
    asm volatile("cp.async.cg.shared.global [%0], [%1], 16;" :: "r"(s), "l"(g));
}
__device__ __forceinline__ void cp_commit() { asm volatile("cp.async.commit_group;"); }
template<int N> __device__ __forceinline__ void cp_wait() {
    asm volatile("cp.async.wait_group %0;" :: "n"(N));
}

__device__ __forceinline__ void mma_f16(float c[4],
                                        unsigned a0, unsigned a1, unsigned a2, unsigned a3,
                                        unsigned b0, unsigned b1) {
    asm volatile(
        "mma.sync.aligned.m16n8k16.row.col.f32.f16.f16.f32 "
        "{%0,%1,%2,%3}, {%4,%5,%6,%7}, {%8,%9}, {%0,%1,%2,%3};"
        : "+f"(c[0]), "+f"(c[1]), "+f"(c[2]), "+f"(c[3])
        : "r"(a0), "r"(a1), "r"(a2), "r"(a3), "r"(b0), "r"(b1));
}

__device__ __forceinline__ void ldsm_x4(unsigned r[4], unsigned addr) {
    asm volatile("ldmatrix.sync.aligned.m8n8.x4.shared.b16 {%0,%1,%2,%3}, [%4];"
                 : "=r"(r[0]), "=r"(r[1]), "=r"(r[2]), "=r"(r[3]) : "r"(addr));
}
__device__ __forceinline__ void ldsm_x4_t(unsigned r[4], unsigned addr) {
    asm volatile("ldmatrix.sync.aligned.m8n8.x4.trans.shared.b16 {%0,%1,%2,%3}, [%4];"
                 : "=r"(r[0]), "=r"(r[1]), "=r"(r[2]), "=r"(r[3]) : "r"(addr));
}
__device__ __forceinline__ unsigned pack2(float lo, float hi) {
    unsigned d;
    asm("cvt.rn.f16x2.f32 %0, %1, %2;" : "=r"(d) : "f"(hi), "f"(lo));
    return d;
}
__device__ __forceinline__ unsigned ex2h2(unsigned x) {
    unsigned d;
    asm("ex2.approx.f16x2 %0, %1;" : "=r"(d) : "r"(x));
    return d;
}

// ================= fused fp32 -> fp16 conversion (one launch, 7 segments) =============
__global__ __launch_bounds__(256)
void f2h_all(const float* __restrict__ hidden,
             const float* __restrict__ wq, const float* __restrict__ wk,
             const float* __restrict__ wv, const float* __restrict__ wo,
             const float* __restrict__ w1, const float* __restrict__ w2,
             __half* __restrict__ hh, __half* __restrict__ wqh,
             __half* __restrict__ wkh, __half* __restrict__ wvh,
             __half* __restrict__ woh, __half* __restrict__ w1h,
             __half* __restrict__ w2h) {
    int blk = blockIdx.x;
    const float* in; __half* out;
    if      (blk < 4096) { in = hidden; out = hh; }
    else if (blk < 5120) { in = wq; out = wqh; blk -= 4096; }
    else if (blk < 5376) { in = wk; out = wkh; blk -= 5120; }
    else if (blk < 5632) { in = wv; out = wvh; blk -= 5376; }
    else if (blk < 6656) { in = wo; out = woh; blk -= 5632; }
    else if (blk < 7680) { in = w1; out = w1h; blk -= 6656; }
    else                 { in = w2; out = w2h; blk -= 7680; }
    int i = blk * 1024 + threadIdx.x * 4;
    float4 v = *(const float4*)(in + i);
    *(__half2*)(out + i)     = __floats2half2_rn(v.x, v.y);
    *(__half2*)(out + i + 2) = __floats2half2_rn(v.z, v.w);
}

// ======== fp16 GEMM: 128x128 block, 8 warps x (64x32), BK=32, 2-stage ========
// Halves L2 traffic vs 64x64 tiles (A re-read 8x, W 32x) while keeping
// 4 warps/SMSP (2 blocks/SM) for latency hiding.
#define GP 40
template<int MODE>
__device__ __forceinline__ void gemm_body(
    const __half* __restrict__ A, const __half* __restrict__ Wb,
    const float* __restrict__ biasl, const float* __restrict__ res,
    void* Cv, int N, int ncol0, int K, int bm, float scale)
{
    __shared__ alignas(16) __half As[2][128 * GP];
    __shared__ alignas(16) __half Ws[2][128 * GP];

    const int tid = threadIdx.x, lane = tid & 31, w = tid >> 5;
    const int wm = w & 1, wn = w >> 1;          // 2m x 4n warps: 64x32 tiles
    const int qr = lane >> 2, qc = lane & 3;
    const int lrow = lane & 15, lcolh = (lane >> 4) << 3;

    const __half* Ab = A + (size_t)bm * 128 * K;

    float acc[4][4][4] = {};                    // 64 accum regs
    const int NK = K / 32;

    auto stage = [&](int kt, int bf) {
        #pragma unroll
        for (int i = 0; i < 2; i++) {           // A: 512 chunks of 16B, 256 thr -> 2 each
            int idx = i * 256 + tid;
            int r = idx >> 2, ch = (idx & 3) * 8;
            cp16(su32(&As[bf][r * GP + ch]), Ab + (size_t)r * K + kt * 32 + ch);
        }
        #pragma unroll
        for (int i = 0; i < 2; i++) {           // W: 512 chunks
            int idx = i * 256 + tid;
            int r = idx >> 2, ch = (idx & 3) * 8;
            cp16(su32(&Ws[bf][r * GP + ch]), Wb + (size_t)r * K + kt * 32 + ch);
        }
    };

    stage(0, 0);
    cp_commit();

    for (int kt = 0; kt < NK; kt++) {
        const int buf = kt & 1;
        if (kt + 1 < NK) {
            stage(kt + 1, buf ^ 1);
            cp_commit();
            cp_wait<1>();
        } else {
            cp_wait<0>();
        }
        __syncthreads();

        const __half* as = As[buf];
        const __half* ws = Ws[buf];
        #pragma unroll
        for (int ks = 0; ks < 2; ks++) {
            unsigned a[4][4], bfr[4][2];
            #pragma unroll
            for (int mt = 0; mt < 4; mt++)
                ldsm_x4(a[mt], su32(&as[(wm * 64 + mt * 16 + lrow) * GP + ks * 16 + lcolh]));
            #pragma unroll
            for (int p = 0; p < 2; p++) {
                unsigned t[4];
                ldsm_x4(t, su32(&ws[(wn * 32 + p * 16 + lrow) * GP + ks * 16 + lcolh]));
                bfr[2 * p][0] = t[0]; bfr[2 * p][1] = t[2];
                bfr[2 * p + 1][0] = t[1]; bfr[2 * p + 1][1] = t[3];
            }
            #pragma unroll
            for (int mt = 0; mt < 4; mt++)
                #pragma unroll
                for (int nt = 0; nt < 4; nt++)
                    mma_f16(acc[mt][nt], a[mt][0], a[mt][1], a[mt][2], a[mt][3],
                            bfr[nt][0], bfr[nt][1]);
        }
        __syncthreads();
    }

    #pragma unroll
    for (int mt = 0; mt < 4; mt++) {
        #pragma unroll
        for (int nt = 0; nt < 4; nt++) {
            int lcol = wn * 32 + nt * 8 + qc * 2;
            int col  = ncol0 + lcol;
            float b0 = biasl[lcol], b1 = biasl[lcol + 1];
            #pragma unroll
            for (int half = 0; half < 2; half++) {
                int row = bm * 128 + wm * 64 + mt * 16 + qr + half * 8;
                float v0 = acc[mt][nt][half * 2 + 0] + b0;
                float v1 = acc[mt][nt][half * 2 + 1] + b1;
                if (MODE == 1) {
                    v0 += res[(size_t)row * N + col];
                    v1 += res[(size_t)row * N + col + 1];
                    float2 o; o.x = v0; o.y = v1;
                    *(float2*)&((float*)Cv)[(size_t)row * N + col] = o;
                } else {
                    if (MODE == 0) { v0 *= scale; v1 *= scale; }
                    if (MODE == 2) { v0 = fmaxf(v0, 0.f); v1 = fmaxf(v1, 0.f); }
                    *(__half2*)&((__half*)Cv)[(size_t)row * N + col] =
                        __floats2half2_rn(v0, v1);
                }
            }
        }
    }
}

template<int MODE>
__global__ __launch_bounds__(256)
void gemm_h(const __half* __restrict__ A, const __half* __restrict__ W,
            const float* __restrict__ bias, const float* __restrict__ res,
            void* C, int N, int K) {
    int bn = blockIdx.x;
    gemm_body<MODE>(A, W + (size_t)bn * 128 * K, bias + bn * 128, res, C,
                    N, bn * 128, K, blockIdx.y, 1.0f);
}

__global__ __launch_bounds__(256)
void qkv_h(const __half* __restrict__ hidden,
           const __half* __restrict__ wq, const float* __restrict__ bq,
           const __half* __restrict__ wk, const float* __restrict__ bk,
           const __half* __restrict__ wv, const float* __restrict__ bv,
           __half* __restrict__ q, __half* __restrict__ k, __half* __restrict__ v) {
    int bn = blockIdx.x;
    const __half* W; const float* bias; __half* C; int N, nc; float sc = 1.0f;
    // q pre-scaled by (1/8)*log2(e): flash computes P = 2^S directly
    if (bn < 8)       { int j = bn;      W = wq + (size_t)j * 128 * HID; bias = bq + j * 128; C = q; N = HID; nc = j * 128; sc = 0.125f * 1.44269504f; }
    else if (bn < 10) { int j = bn - 8;  W = wk + (size_t)j * 128 * HID; bias = bk + j * 128; C = k; N = KVW; nc = j * 128; }
    else              { int j = bn - 10; W = wv + (size_t)j * 128 * HID; bias = bv + j * 128; C = v; N = KVW; nc = j * 128; }
    gemm_body<0>(hidden, W, bias, nullptr, C, N, nc, HID, blockIdx.y, sc);
}

// ================= flash attention fp16: ex2.f16x2 softmax + ones-mma row sums ========
#define FP 72
#define ONESH2 0x3C003C00u
__global__ __launch_bounds__(256)
void flash7(const __half* __restrict__ qh, const __half* __restrict__ kh,
            const __half* __restrict__ vh, __half* __restrict__ Xh) {
    __shared__ alignas(16) __half Ks[2][32 * FP];
    __shared__ alignas(16) __half Vs[2][32 * FP];

    const int b = blockIdx.z, h = blockIdx.y, qt = blockIdx.x, g = h >> 2;
    const int tid = threadIdx.x, lane = tid & 31, w = tid >> 5;
    const int qr = lane >> 2, qc = lane & 3;
    const int lrow = lane & 15, lcolh = (lane >> 4) << 3;

    unsigned qa[2][4][4];
    #pragma unroll
    for (int mt = 0; mt < 2; mt++) {
        const __half2* q2 = (const __half2*)(qh +
            (size_t)(b * SEQ + qt * 256 + w * 32 + mt * 16) * HID + h * 64);
        #pragma unroll
        for (int ks = 0; ks < 4; ks++) {
            qa[mt][ks][0] = *(const unsigned*)&q2[(size_t)qr       * 512 + ks * 8 + qc];
            qa[mt][ks][1] = *(const unsigned*)&q2[(size_t)(qr + 8) * 512 + ks * 8 + qc];
            qa[mt][ks][2] = *(const unsigned*)&q2[(size_t)qr       * 512 + ks * 8 + qc + 4];
            qa[mt][ks][3] = *(const unsigned*)&q2[(size_t)(qr + 8) * 512 + ks * 8 + qc + 4];
        }
    }

    float lacc[2][4] = {};
    float O[2][8][4] = {};

    const __half* kb = kh + (size_t)b * SEQ * KVW + g * 64;
    const __half* vb = vh + (size_t)b * SEQ * KVW + g * 64;

    const int r = tid >> 3;
    const int ch = (tid & 7) * 8;
    auto stage = [&](int kt, int bf) {
        cp16(su32(&Ks[bf][r * FP + ch]), kb + (size_t)(kt * 32 + r) * KVW + ch);
        cp16(su32(&Vs[bf][r * FP + ch]), vb + (size_t)(kt * 32 + r) * KVW + ch);
    };

    stage(0, 0);
    cp_commit();

    const int NT = SEQ / 32;
    for (int kt = 0; kt < NT; kt++) {
        const int buf = kt & 1;
        __syncthreads();
        if (kt + 1 < NT) {
            stage(kt + 1, buf ^ 1);
            cp_commit();
            cp_wait<1>();
        } else {
            cp_wait<0>();
        }
        __syncthreads();

        const __half* ks_ = Ks[buf];
        const __half* vs_ = Vs[buf];

        float S[2][4][4] = {};
        #pragma unroll
        for (int ks = 0; ks < 4; ks++) {
            unsigned kf[4][2];
            #pragma unroll
            for (int p = 0; p < 2; p++) {
                unsigned t[4];
                ldsm_x4(t, su32(&ks_[(p * 16 + lrow) * FP + ks * 16 + lcolh]));
                kf[2 * p][0] = t[0]; kf[2 * p][1] = t[2];
                kf[2 * p + 1][0] = t[1]; kf[2 * p + 1][1] = t[3];
            }
            #pragma unroll
            for (int nt = 0; nt < 4; nt++) {
                mma_f16(S[0][nt], qa[0][ks][0], qa[0][ks][1], qa[0][ks][2], qa[0][ks][3],
                        kf[nt][0], kf[nt][1]);
                mma_f16(S[1][nt], qa[1][ks][0], qa[1][ks][1], qa[1][ks][2], qa[1][ks][3],
                        kf[nt][0], kf[nt][1]);
            }
        }

        unsigned Pf[2][4][2];
        #pragma unroll
        for (int mt = 0; mt < 2; mt++) {
            #pragma unroll
            for (int nt = 0; nt < 4; nt++) {
                Pf[mt][nt][0] = ex2h2(pack2(S[mt][nt][0], S[mt][nt][1]));
                Pf[mt][nt][1] = ex2h2(pack2(S[mt][nt][2], S[mt][nt][3]));
            }
        }

        #pragma unroll
        for (int ks2 = 0; ks2 < 2; ks2++) {
            unsigned amt[2][4];
            #pragma unroll
            for (int mt = 0; mt < 2; mt++) {
                amt[mt][0] = Pf[mt][2 * ks2][0];
                amt[mt][1] = Pf[mt][2 * ks2][1];
                amt[mt][2] = Pf[mt][2 * ks2 + 1][0];
                amt[mt][3] = Pf[mt][2 * ks2 + 1][1];
            }
            mma_f16(lacc[0], amt[0][0], amt[0][1], amt[0][2], amt[0][3], ONESH2, ONESH2);
            mma_f16(lacc[1], amt[1][0], amt[1][1], amt[1][2], amt[1][3], ONESH2, ONESH2);

            unsigned vf[8][2];
            #pragma unroll
            for (int p = 0; p < 4; p++) {
                unsigned t[4];
                ldsm_x4_t(t, su32(&vs_[(ks2 * 16 + lrow) * FP + p * 16 + lcolh]));
                vf[2 * p][0] = t[0]; vf[2 * p][1] = t[1];
                vf[2 * p + 1][0] = t[2]; vf[2 * p + 1][1] = t[3];
            }
            #pragma unroll
            for (int nt = 0; nt < 8; nt++) {
                mma_f16(O[0][nt], amt[0][0], amt[0][1], amt[0][2], amt[0][3],
                        vf[nt][0], vf[nt][1]);
                mma_f16(O[1][nt], amt[1][0], amt[1][1], amt[1][2], amt[1][3],
                        vf[nt][0], vf[nt][1]);
            }
        }
    }

    __half* Xb = Xh + (size_t)b * SEQ * HID;
    #pragma unroll
    for (int mt = 0; mt < 2; mt++) {
        float inv0 = 1.f / lacc[mt][0];
        float inv1 = 1.f / lacc[mt][2];

        int s0 = qt * 256 + w * 32 + mt * 16 + qr;
        int s1 = s0 + 8;
        int col0 = s0 & 1023, bit0 = s0 >> 10;
        int col1 = s1 & 1023, bit1 = s1 >> 10;
        #pragma unroll
        for (int nt = 0; nt < 8; nt++) {
            #pragma unroll
            for (int j = 0; j < 2; j++) {
                int d = nt * 8 + qc * 2 + j;
                Xb[(size_t)(h * 128 + 2 * d + bit0) * HID + col0] = __float2half(O[mt][nt][j]     * inv0);
                Xb[(size_t)(h * 128 + 2 * d + bit1) * HID + col1] = __float2half(O[mt][nt][2 + j] * inv1);
            }
        }
    }
}

// ================= row LayerNorm (vectorized, optional fp16 secondary output) =========
template<int H16>
__global__ __launch_bounds__(256)
void lnorm(const float* __restrict__ xin, const float* __restrict__ gw,
           const float* __restrict__ bw, float* __restrict__ yout,
           __half* __restrict__ yh) {
    __shared__ float rs[8], rs2[8];
    const int row = blockIdx.x;
    const float4* x4 = (const float4*)(xin + (size_t)row * HID);

    float4 v = x4[threadIdx.x];
    float s  = v.x + v.y + v.z + v.w;
    float s2 = v.x * v.x + v.y * v.y + v.z * v.z + v.w * v.w;
    #pragma unroll
    for (int off = 16; off; off >>= 1) {
        s  += __shfl_xor_sync(0xffffffffu, s,  off);
        s2 += __shfl_xor_sync(0xffffffffu, s2, off);
    }
    int wid = threadIdx.x >> 5, lane = threadIdx.x & 31;
    if (lane == 0) { rs[wid] = s; rs2[wid] = s2; }
    __syncthreads();
    float ts = 0.f, ts2 = 0.f;
    #pragma unroll
    for (int i = 0; i < 8; i++) { ts += rs[i]; ts2 += rs2[i]; }

    float mu  = ts * (1.f / HID);
    float var = ts2 * (1.f / HID) - mu * mu;
    float rstd = rsqrtf(var + 1e-5f);

    float4 g4 = ((const float4*)gw)[threadIdx.x];
    float4 b4 = ((const float4*)bw)[threadIdx.x];
    float4 y;
    y.x = (v.x - mu) * rstd * g4.x + b4.x;
    y.y = (v.y - mu) * rstd * g4.y + b4.y;
    y.z = (v.z - mu) * rstd * g4.z + b4.z;
    y.w = (v.w - mu) * rstd * g4.w + b4.w;
    ((float4*)(yout + (size_t)row * HID))[threadIdx.x] = y;
    if (H16) {
        __half* yp = yh + (size_t)row * HID + threadIdx.x * 4;
        *(__half2*)yp       = __floats2half2_rn(y.x, y.y);
        *(__half2*)(yp + 2) = __floats2half2_rn(y.z, y.w);
    }
}

// ================= launch =================
extern "C" void kernel_launch(void* const* d_in, const int* in_sizes, int n_in,
                              void* d_out, int out_size) {
    const float* hidden = (const float*)d_in[0];
    const float* wq = (const float*)d_in[1];  const float* bq = (const float*)d_in[2];
    const float* wk = (const float*)d_in[3];  const float* bk = (const float*)d_in[4];
    const float* wv = (const float*)d_in[5];  const float* bv = (const float*)d_in[6];
    const float* wo = (const float*)d_in[7];  const float* bo = (const float*)d_in[8];
    const float* lng = (const float*)d_in[9]; const float* lnb = (const float*)d_in[10];
    const float* w1 = (const float*)d_in[11]; const float* b1 = (const float*)d_in[12];
    const float* w2 = (const float*)d_in[13]; const float* b2 = (const float*)d_in[14];
    const float* flng = (const float*)d_in[15]; const float* flnb = (const float*)d_in[16];
    float* out = (float*)d_out;

    float *t1, *o;
    __half *hh, *wqh, *wkh, *wvh, *woh, *w1h, *w2h, *qh, *kh, *vh, *xh, *oh, *f1h;
    cudaGetSymbolAddress((void**)&t1,  g_t1);
    cudaGetSymbolAddress((void**)&o,   g_o);
    cudaGetSymbolAddress((void**)&hh,  g_hh);
    cudaGetSymbolAddress((void**)&wqh, g_wqh);
    cudaGetSymbolAddress((void**)&wkh, g_wkh);
    cudaGetSymbolAddress((void**)&wvh, g_wvh);
    cudaGetSymbolAddress((void**)&woh, g_woh);
    cudaGetSymbolAddress((void**)&w1h, g_w1h);
    cudaGetSymbolAddress((void**)&w2h, g_w2h);
    cudaGetSymbolAddress((void**)&qh,  g_qh);
    cudaGetSymbolAddress((void**)&kh,  g_kh);
    cudaGetSymbolAddress((void**)&vh,  g_vh);
    cudaGetSymbolAddress((void**)&xh,  g_xh);
    cudaGetSymbolAddress((void**)&oh,  g_oh);
    cudaGetSymbolAddress((void**)&f1h, g_f1h);

    // fp32 -> fp16 prep (single fused launch)
    f2h_all<<<8704, 256>>>(hidden, wq, wk, wv, wo, w1, w2,
                           hh, wqh, wkh, wvh, woh, w1h, w2h);

    // fused QKV projections (128x128 tiles; q pre-scaled by log2(e)/8)
    qkv_h<<<dim3(12, TOK / 128), 256>>>(hh, wqh, bq, wkh, bk, wvh, bv, qh, kh, vh);

    // fused GQA attention -> scrambled fp16 X
    flash7<<<dim3(SEQ / 256, 16, 2), 256>>>(qh, kh, vh, xh);

    // O-proj + residual (fp32), LN -> o (fp32) + oh (fp16)
    gemm_h<1><<<dim3(HID / 128, TOK / 128), 256>>>(xh, woh, bo, hidden, t1, HID, HID);
    lnorm<1><<<TOK, 256>>>(t1, lng, lnb, o, oh);

    // FFN
    gemm_h<2><<<dim3(HID / 128, TOK / 128), 256>>>(oh, w1h, b1, nullptr, f1h, HID, HID);
    gemm_h<1><<<dim3(HID / 128, TOK / 128), 256>>>(f1h, w2h, b2, o, t1, HID, HID);
    lnorm<0><<<TOK, 256>>>(t1, flng, flnb, out, nullptr);
}

// round 17
// speedup vs baseline: 1.0621x; 1.0621x over previous
#include <cuda_runtime.h>
#include <cuda_fp16.h>
#include <cstdint>

#define TOK 4096
#define HID 1024
#define KVW 256
#define SEQ 2048

// fp32 scratch
__device__ float g_t1[TOK * HID];
__device__ float g_o [TOK * HID];
// fp16 scratch
__device__ __half g_hh [TOK * HID];
__device__ __half g_wqh[HID * HID];
__device__ __half g_wkh[KVW * HID];
__device__ __half g_wvh[KVW * HID];
__device__ __half g_woh[HID * HID];
__device__ __half g_w1h[HID * HID];
__device__ __half g_w2h[HID * HID];
__device__ __half g_qh [TOK * HID];
__device__ __half g_kh [TOK * KVW];
__device__ __half g_vh [TOK * KVW];
__device__ __half g_xh [TOK * HID];
__device__ __half g_oh [TOK * HID];
__device__ __half g_f1h[TOK * HID];

__device__ __forceinline__ unsigned su32(const void* p) {
    return (unsigned)__cvta_generic_to_shared(p);
}
__device__ __forceinline__ void cp16(unsigned s, const void* g) {
    asm volatile("cp.async.cg.shared.global [%0], [%1], 16;" :: "r"(s), "l"(g));
}
__device__ __forceinline__ void cp_commit() { asm volatile("cp.async.commit_group;"); }
template<int N> __device__ __forceinline__ void cp_wait() {
    asm volatile("cp.async.wait_group %0;" :: "n"(N));
}

__device__ __forceinline__ void mma_f16(float c[4],
                                        unsigned a0, unsigned a1, unsigned a2, unsigned a3,
                                        unsigned b0, unsigned b1) {
    asm volatile(
        "mma.sync.aligned.m16n8k16.row.col.f32.f16.f16.f32 "
        "{%0,%1,%2,%3}, {%4,%5,%6,%7}, {%8,%9}, {%0,%1,%2,%3};"
        : "+f"(c[0]), "+f"(c[1]), "+f"(c[2]), "+f"(c[3])
        : "r"(a0), "r"(a1), "r"(a2), "r"(a3), "r"(b0), "r"(b1));
}

__device__ __forceinline__ void ldsm_x4(unsigned r[4], unsigned addr) {
    asm volatile("ldmatrix.sync.aligned.m8n8.x4.shared.b16 {%0,%1,%2,%3}, [%4];"
                 : "=r"(r[0]), "=r"(r[1]), "=r"(r[2]), "=r"(r[3]) : "r"(addr));
}
__device__ __forceinline__ void ldsm_x4_t(unsigned r[4], unsigned addr) {
    asm volatile("ldmatrix.sync.aligned.m8n8.x4.trans.shared.b16 {%0,%1,%2,%3}, [%4];"
                 : "=r"(r[0]), "=r"(r[1]), "=r"(r[2]), "=r"(r[3]) : "r"(addr));
}
__device__ __forceinline__ unsigned pack2(float lo, float hi) {
    unsigned d;
    asm("cvt.rn.f16x2.f32 %0, %1, %2;" : "=r"(d) : "f"(hi), "f"(lo));
    return d;
}
__device__ __forceinline__ unsigned ex2h2(unsigned x) {
    unsigned d;
    asm("ex2.approx.f16x2 %0, %1;" : "=r"(d) : "r"(x));
    return d;
}

// ================= fused fp32 -> fp16 conversion (one launch, 7 segments) =============
__global__ __launch_bounds__(256)
void f2h_all(const float* __restrict__ hidden,
             const float* __restrict__ wq, const float* __restrict__ wk,
             const float* __restrict__ wv, const float* __restrict__ wo,
             const float* __restrict__ w1, const float* __restrict__ w2,
             __half* __restrict__ hh, __half* __restrict__ wqh,
             __half* __restrict__ wkh, __half* __restrict__ wvh,
             __half* __restrict__ woh, __half* __restrict__ w1h,
             __half* __restrict__ w2h) {
    int blk = blockIdx.x;
    const float* in; __half* out;
    if      (blk < 4096) { in = hidden; out = hh; }
    else if (blk < 5120) { in = wq; out = wqh; blk -= 4096; }
    else if (blk < 5376) { in = wk; out = wkh; blk -= 5120; }
    else if (blk < 5632) { in = wv; out = wvh; blk -= 5376; }
    else if (blk < 6656) { in = wo; out = woh; blk -= 5632; }
    else if (blk < 7680) { in = w1; out = w1h; blk -= 6656; }
    else                 { in = w2; out = w2h; blk -= 7680; }
    int i = blk * 1024 + threadIdx.x * 4;
    float4 v = *(const float4*)(in + i);
    *(__half2*)(out + i)     = __floats2half2_rn(v.x, v.y);
    *(__half2*)(out + i + 2) = __floats2half2_rn(v.z, v.w);
}

// ================= fp16 GEMM: 64x128 block, 4 warps x (32x64), BK=32 (round-12) =======
#define GP 40
template<int MODE>
__device__ __forceinline__ void gemm_body(
    const __half* __restrict__ A, const __half* __restrict__ Wb,
    const float* __restrict__ biasl, const float* __restrict__ res,
    void* Cv, int N, int ncol0, int K, int bm, float scale)
{
    __shared__ alignas(16) __half As[2][64 * GP];
    __shared__ alignas(16) __half Ws[2][128 * GP];

    const int tid = threadIdx.x, lane = tid & 31, w = tid >> 5;
    const int wm = w & 1, wn = w >> 1;          // 2m x 2n warps: 32x64 tiles
    const int qr = lane >> 2, qc = lane & 3;
    const int lrow = lane & 15, lcolh = (lane >> 4) << 3;

    const __half* Ab = A + (size_t)bm * 64 * K;

    float acc[2][8][4] = {};
    const int NK = K / 32;

    auto stage = [&](int kt, int bf) {
        #pragma unroll
        for (int i = 0; i < 2; i++) {           // A: 256 chunks
            int idx = i * 128 + tid;
            int r = idx >> 2, ch = (idx & 3) * 8;
            cp16(su32(&As[bf][r * GP + ch]), Ab + (size_t)r * K + kt * 32 + ch);
        }
        #pragma unroll
        for (int i = 0; i < 4; i++) {           // W: 512 chunks
            int idx = i * 128 + tid;
            int r = idx >> 2, ch = (idx & 3) * 8;
            cp16(su32(&Ws[bf][r * GP + ch]), Wb + (size_t)r * K + kt * 32 + ch);
        }
    };

    stage(0, 0);
    cp_commit();

    for (int kt = 0; kt < NK; kt++) {
        const int buf = kt & 1;
        if (kt + 1 < NK) {
            stage(kt + 1, buf ^ 1);
            cp_commit();
            cp_wait<1>();
        } else {
            cp_wait<0>();
        }
        __syncthreads();

        const __half* as = As[buf];
        const __half* ws = Ws[buf];
        #pragma unroll
        for (int ks = 0; ks < 2; ks++) {
            unsigned a[2][4], bfr[8][2];
            #pragma unroll
            for (int mt = 0; mt < 2; mt++)
                ldsm_x4(a[mt], su32(&as[(wm * 32 + mt * 16 + lrow) * GP + ks * 16 + lcolh]));
            #pragma unroll
            for (int p = 0; p < 4; p++) {
                unsigned t[4];
                ldsm_x4(t, su32(&ws[(wn * 64 + p * 16 + lrow) * GP + ks * 16 + lcolh]));
                bfr[2 * p][0] = t[0]; bfr[2 * p][1] = t[2];
                bfr[2 * p + 1][0] = t[1]; bfr[2 * p + 1][1] = t[3];
            }
            #pragma unroll
            for (int mt = 0; mt < 2; mt++)
                #pragma unroll
                for (int nt = 0; nt < 8; nt++)
                    mma_f16(acc[mt][nt], a[mt][0], a[mt][1], a[mt][2], a[mt][3],
                            bfr[nt][0], bfr[nt][1]);
        }
        __syncthreads();
    }

    #pragma unroll
    for (int mt = 0; mt < 2; mt++) {
        #pragma unroll
        for (int nt = 0; nt < 8; nt++) {
            int lcol = wn * 64 + nt * 8 + qc * 2;
            int col  = ncol0 + lcol;
            float b0 = biasl[lcol], b1 = biasl[lcol + 1];
            #pragma unroll
            for (int half = 0; half < 2; half++) {
                int row = bm * 64 + wm * 32 + mt * 16 + qr + half * 8;
                float v0 = acc[mt][nt][half * 2 + 0] + b0;
                float v1 = acc[mt][nt][half * 2 + 1] + b1;
                if (MODE == 1) {
                    v0 += res[(size_t)row * N + col];
                    v1 += res[(size_t)row * N + col + 1];
                    float2 o; o.x = v0; o.y = v1;
                    *(float2*)&((float*)Cv)[(size_t)row * N + col] = o;
                } else {
                    if (MODE == 0) { v0 *= scale; v1 *= scale; }
                    if (MODE == 2) { v0 = fmaxf(v0, 0.f); v1 = fmaxf(v1, 0.f); }
                    *(__half2*)&((__half*)Cv)[(size_t)row * N + col] =
                        __floats2half2_rn(v0, v1);
                }
            }
        }
    }
}

template<int MODE>
__global__ __launch_bounds__(128)
void gemm_h(const __half* __restrict__ A, const __half* __restrict__ W,
            const float* __restrict__ bias, const float* __restrict__ res,
            void* C, int N, int K) {
    int bn = blockIdx.x;
    gemm_body<MODE>(A, W + (size_t)bn * 128 * K, bias + bn * 128, res, C,
                    N, bn * 128, K, blockIdx.y, 1.0f);
}

__global__ __launch_bounds__(128)
void qkv_h(const __half* __restrict__ hidden,
           const __half* __restrict__ wq, const float* __restrict__ bq,
           const __half* __restrict__ wk, const float* __restrict__ bk,
           const __half* __restrict__ wv, const float* __restrict__ bv,
           __half* __restrict__ q, __half* __restrict__ k, __half* __restrict__ v) {
    int bn = blockIdx.x;
    const __half* W; const float* bias; __half* C; int N, nc; float sc = 1.0f;
    // q pre-scaled by (1/8)*log2(e): flash computes P = 2^S directly
    if (bn < 8)       { int j = bn;      W = wq + (size_t)j * 128 * HID; bias = bq + j * 128; C = q; N = HID; nc = j * 128; sc = 0.125f * 1.44269504f; }
    else if (bn < 10) { int j = bn - 8;  W = wk + (size_t)j * 128 * HID; bias = bk + j * 128; C = k; N = KVW; nc = j * 128; }
    else              { int j = bn - 10; W = wv + (size_t)j * 128 * HID; bias = bv + j * 128; C = v; N = KVW; nc = j * 128; }
    gemm_body<0>(hidden, W, bias, nullptr, C, N, nc, HID, blockIdx.y, sc);
}

// ===== flash attention fp16: 64-key staged tiles (2x32 halves), halved barrier count ===
#define FP 72
#define ONESH2 0x3C003C00u
__global__ __launch_bounds__(256)
void flash8(const __half* __restrict__ qh, const __half* __restrict__ kh,
            const __half* __restrict__ vh, __half* __restrict__ Xh) {
    __shared__ alignas(16) __half Ks[2][64 * FP];
    __shared__ alignas(16) __half Vs[2][64 * FP];

    const int b = blockIdx.z, h = blockIdx.y, qt = blockIdx.x, g = h >> 2;
    const int tid = threadIdx.x, lane = tid & 31, w = tid >> 5;
    const int qr = lane >> 2, qc = lane & 3;
    const int lrow = lane & 15, lcolh = (lane >> 4) << 3;

    unsigned qa[2][4][4];
    #pragma unroll
    for (int mt = 0; mt < 2; mt++) {
        const __half2* q2 = (const __half2*)(qh +
            (size_t)(b * SEQ + qt * 256 + w * 32 + mt * 16) * HID + h * 64);
        #pragma unroll
        for (int ks = 0; ks < 4; ks++) {
            qa[mt][ks][0] = *(const unsigned*)&q2[(size_t)qr       * 512 + ks * 8 + qc];
            qa[mt][ks][1] = *(const unsigned*)&q2[(size_t)(qr + 8) * 512 + ks * 8 + qc];
            qa[mt][ks][2] = *(const unsigned*)&q2[(size_t)qr       * 512 + ks * 8 + qc + 4];
            qa[mt][ks][3] = *(const unsigned*)&q2[(size_t)(qr + 8) * 512 + ks * 8 + qc + 4];
        }
    }

    float lacc[2][4] = {};
    float O[2][8][4] = {};

    const __half* kb = kh + (size_t)b * SEQ * KVW + g * 64;
    const __half* vb = vh + (size_t)b * SEQ * KVW + g * 64;

    // stage 64 rows x 128B per tensor = 512 chunks; thread: 2 K + 2 V chunks
    auto stage = [&](int kt, int bf) {
        #pragma unroll
        for (int i = 0; i < 2; i++) {
            int idx = i * 256 + tid;
            int r = idx >> 3, ch = (idx & 7) * 8;
            cp16(su32(&Ks[bf][r * FP + ch]), kb + (size_t)(kt * 64 + r) * KVW + ch);
            cp16(su32(&Vs[bf][r * FP + ch]), vb + (size_t)(kt * 64 + r) * KVW + ch);
        }
    };

    stage(0, 0);
    cp_commit();

    const int NT = SEQ / 64;
    for (int kt = 0; kt < NT; kt++) {
        const int buf = kt & 1;
        __syncthreads();
        if (kt + 1 < NT) {
            stage(kt + 1, buf ^ 1);
            cp_commit();
            cp_wait<1>();
        } else {
            cp_wait<0>();
        }
        __syncthreads();

        // two 32-key halves; registers reused across halves
        #pragma unroll
        for (int half = 0; half < 2; half++) {
            const __half* ks_ = Ks[buf] + half * 32 * FP;
            const __half* vs_ = Vs[buf] + half * 32 * FP;

            float S[2][4][4] = {};
            #pragma unroll
            for (int ks = 0; ks < 4; ks++) {
                unsigned kf[4][2];
                #pragma unroll
                for (int p = 0; p < 2; p++) {
                    unsigned t[4];
                    ldsm_x4(t, su32(&ks_[(p * 16 + lrow) * FP + ks * 16 + lcolh]));
                    kf[2 * p][0] = t[0]; kf[2 * p][1] = t[2];
                    kf[2 * p + 1][0] = t[1]; kf[2 * p + 1][1] = t[3];
                }
                #pragma unroll
                for (int nt = 0; nt < 4; nt++) {
                    mma_f16(S[0][nt], qa[0][ks][0], qa[0][ks][1], qa[0][ks][2], qa[0][ks][3],
                            kf[nt][0], kf[nt][1]);
                    mma_f16(S[1][nt], qa[1][ks][0], qa[1][ks][1], qa[1][ks][2], qa[1][ks][3],
                            kf[nt][0], kf[nt][1]);
                }
            }

            unsigned Pf[2][4][2];
            #pragma unroll
            for (int mt = 0; mt < 2; mt++) {
                #pragma unroll
                for (int nt = 0; nt < 4; nt++) {
                    Pf[mt][nt][0] = ex2h2(pack2(S[mt][nt][0], S[mt][nt][1]));
                    Pf[mt][nt][1] = ex2h2(pack2(S[mt][nt][2], S[mt][nt][3]));
                }
            }

            #pragma unroll
            for (int ks2 = 0; ks2 < 2; ks2++) {
                unsigned amt[2][4];
                #pragma unroll
                for (int mt = 0; mt < 2; mt++) {
                    amt[mt][0] = Pf[mt][2 * ks2][0];
                    amt[mt][1] = Pf[mt][2 * ks2][1];
                    amt[mt][2] = Pf[mt][2 * ks2 + 1][0];
                    amt[mt][3] = Pf[mt][2 * ks2 + 1][1];
                }
                mma_f16(lacc[0], amt[0][0], amt[0][1], amt[0][2], amt[0][3], ONESH2, ONESH2);
                mma_f16(lacc[1], amt[1][0], amt[1][1], amt[1][2], amt[1][3], ONESH2, ONESH2);

                unsigned vf[8][2];
                #pragma unroll
                for (int p = 0; p < 4; p++) {
                    unsigned t[4];
                    ldsm_x4_t(t, su32(&vs_[(ks2 * 16 + lrow) * FP + p * 16 + lcolh]));
                    vf[2 * p][0] = t[0]; vf[2 * p][1] = t[1];
                    vf[2 * p + 1][0] = t[2]; vf[2 * p + 1][1] = t[3];
                }
                #pragma unroll
                for (int nt = 0; nt < 8; nt++) {
                    mma_f16(O[0][nt], amt[0][0], amt[0][1], amt[0][2], amt[0][3],
                            vf[nt][0], vf[nt][1]);
                    mma_f16(O[1][nt], amt[1][0], amt[1][1], amt[1][2], amt[1][3],
                            vf[nt][0], vf[nt][1]);
                }
            }
        }
    }

    __half* Xb = Xh + (size_t)b * SEQ * HID;
    #pragma unroll
    for (int mt = 0; mt < 2; mt++) {
        float inv0 = 1.f / lacc[mt][0];
        float inv1 = 1.f / lacc[mt][2];

        int s0 = qt * 256 + w * 32 + mt * 16 + qr;
        int s1 = s0 + 8;
        int col0 = s0 & 1023, bit0 = s0 >> 10;
        int col1 = s1 & 1023, bit1 = s1 >> 10;
        #pragma unroll
        for (int nt = 0; nt < 8; nt++) {
            #pragma unroll
            for (int j = 0; j < 2; j++) {
                int d = nt * 8 + qc * 2 + j;
                Xb[(size_t)(h * 128 + 2 * d + bit0) * HID + col0] = __float2half(O[mt][nt][j]     * inv0);
                Xb[(size_t)(h * 128 + 2 * d + bit1) * HID + col1] = __float2half(O[mt][nt][2 + j] * inv1);
            }
        }
    }
}

// ================= row LayerNorm (vectorized, optional fp16 secondary output) =========
template<int H16>
__global__ __launch_bounds__(256)
void lnorm(const float* __restrict__ xin, const float* __restrict__ gw,
           const float* __restrict__ bw, float* __restrict__ yout,
           __half* __restrict__ yh) {
    __shared__ float rs[8], rs2[8];
    const int row = blockIdx.x;
    const float4* x4 = (const float4*)(xin + (size_t)row * HID);

    float4 v = x4[threadIdx.x];
    float s  = v.x + v.y + v.z + v.w;
    float s2 = v.x * v.x + v.y * v.y + v.z * v.z + v.w * v.w;
    #pragma unroll
    for (int off = 16; off; off >>= 1) {
        s  += __shfl_xor_sync(0xffffffffu, s,  off);
        s2 += __shfl_xor_sync(0xffffffffu, s2, off);
    }
    int wid = threadIdx.x >> 5, lane = threadIdx.x & 31;
    if (lane == 0) { rs[wid] = s; rs2[wid] = s2; }
    __syncthreads();
    float ts = 0.f, ts2 = 0.f;
    #pragma unroll
    for (int i = 0; i < 8; i++) { ts += rs[i]; ts2 += rs2[i]; }

    float mu  = ts * (1.f / HID);
    float var = ts2 * (1.f / HID) - mu * mu;
    float rstd = rsqrtf(var + 1e-5f);

    float4 g4 = ((const float4*)gw)[threadIdx.x];
    float4 b4 = ((const float4*)bw)[threadIdx.x];
    float4 y;
    y.x = (v.x - mu) * rstd * g4.x + b4.x;
    y.y = (v.y - mu) * rstd * g4.y + b4.y;
    y.z = (v.z - mu) * rstd * g4.z + b4.z;
    y.w = (v.w - mu) * rstd * g4.w + b4.w;
    ((float4*)(yout + (size_t)row * HID))[threadIdx.x] = y;
    if (H16) {
        __half* yp = yh + (size_t)row * HID + threadIdx.x * 4;
        *(__half2*)yp       = __floats2half2_rn(y.x, y.y);
        *(__half2*)(yp + 2) = __floats2half2_rn(y.z, y.w);
    }
}

// ================= launch =================
extern "C" void kernel_launch(void* const* d_in, const int* in_sizes, int n_in,
                              void* d_out, int out_size) {
    const float* hidden = (const float*)d_in[0];
    const float* wq = (const float*)d_in[1];  const float* bq = (const float*)d_in[2];
    const float* wk = (const float*)d_in[3];  const float* bk = (const float*)d_in[4];
    const float* wv = (const float*)d_in[5];  const float* bv = (const float*)d_in[6];
    const float* wo = (const float*)d_in[7];  const float* bo = (const float*)d_in[8];
    const float* lng = (const float*)d_in[9]; const float* lnb = (const float*)d_in[10];
    const float* w1 = (const float*)d_in[11]; const float* b1 = (const float*)d_in[12];
    const float* w2 = (const float*)d_in[13]; const float* b2 = (const float*)d_in[14];
    const float* flng = (const float*)d_in[15]; const float* flnb = (const float*)d_in[16];
    float* out = (float*)d_out;

    float *t1, *o;
    __half *hh, *wqh, *wkh, *wvh, *woh, *w1h, *w2h, *qh, *kh, *vh, *xh, *oh, *f1h;
    cudaGetSymbolAddress((void**)&t1,  g_t1);
    cudaGetSymbolAddress((void**)&o,   g_o);
    cudaGetSymbolAddress((void**)&hh,  g_hh);
    cudaGetSymbolAddress((void**)&wqh, g_wqh);
    cudaGetSymbolAddress((void**)&wkh, g_wkh);
    cudaGetSymbolAddress((void**)&wvh, g_wvh);
    cudaGetSymbolAddress((void**)&woh, g_woh);
    cudaGetSymbolAddress((void**)&w1h, g_w1h);
    cudaGetSymbolAddress((void**)&w2h, g_w2h);
    cudaGetSymbolAddress((void**)&qh,  g_qh);
    cudaGetSymbolAddress((void**)&kh,  g_kh);
    cudaGetSymbolAddress((void**)&vh,  g_vh);
    cudaGetSymbolAddress((void**)&xh,  g_xh);
    cudaGetSymbolAddress((void**)&oh,  g_oh);
    cudaGetSymbolAddress((void**)&f1h, g_f1h);

    // fp32 -> fp16 prep (single fused launch)
    f2h_all<<<8704, 256>>>(hidden, wq, wk, wv, wo, w1, w2,
                           hh, wqh, wkh, wvh, woh, w1h, w2h);

    // fused QKV projections (round-12 config; q pre-scaled by log2(e)/8)
    qkv_h<<<dim3(12, TOK / 64), 128>>>(hh, wqh, bq, wkh, bk, wvh, bv, qh, kh, vh);

    // fused GQA attention -> scrambled fp16 X (64-key staged tiles)
    flash8<<<dim3(SEQ / 256, 16, 2), 256>>>(qh, kh, vh, xh);

    // O-proj + residual (fp32), LN -> o (fp32) + oh (fp16)
    gemm_h<1><<<dim3(HID / 128, TOK / 64), 128>>>(xh, woh, bo, hidden, t1, HID, HID);
    lnorm<1><<<TOK, 256>>>(t1, lng, lnb, o, oh);

    // FFN
    gemm_h<2><<<dim3(HID / 128, TOK / 64), 128>>>(oh, w1h, b1, nullptr, f1h, HID, HID);
    gemm_h<1><<<dim3(HID / 128, TOK / 64), 128>>>(f1h, w2h, b2, o, t1, HID, HID);
    lnorm<0><<<TOK, 256>>>(t1, flng, flnb, out, nullptr);
}